// round 1
// baseline (speedup 1.0000x reference)
#include <cuda_runtime.h>
#include <cstdint>

#define USER_N 100000
#define ITEM_N 200000
#define NN     (USER_N + ITEM_N)   // 300000
#define D      64
#define E_NUM  4800000

// Scratch ping-pong buffers for layer embeddings (static device allocation —
// the only legal scratch under the harness allocation guards).
__device__ float g_bufA[(size_t)NN * D];
__device__ float g_bufB[(size_t)NN * D];

// ---------------------------------------------------------------------------
// init: out = concat(u, i) (acc layer-0 term), bufA = same, bufB = 0
// float4-vectorized; USER_N*D and NN*D are multiples of 4.
// ---------------------------------------------------------------------------
__global__ void init_kernel(const float4* __restrict__ u,
                            const float4* __restrict__ i,
                            float4* __restrict__ out,
                            float4* __restrict__ bufA,
                            float4* __restrict__ bufB) {
    const size_t total4 = (size_t)NN * D / 4;
    const size_t usplit = (size_t)USER_N * D / 4;
    size_t idx = (size_t)blockIdx.x * blockDim.x + threadIdx.x;
    if (idx >= total4) return;
    float4 v = (idx < usplit) ? u[idx] : i[idx - usplit];
    out[idx]  = v;
    bufA[idx] = v;
    bufB[idx] = make_float4(0.f, 0.f, 0.f, 0.f);
}

// ---------------------------------------------------------------------------
// COO SpMM scatter: y[rows[e]] += vals[e] * x[cols[e]], 16 threads per edge,
// each thread owns a 16B (float4) slice and issues ONE red.global.add.v4.f32.
// ---------------------------------------------------------------------------
__global__ void __launch_bounds__(256)
spmm_kernel(const int* __restrict__ rows,
            const int* __restrict__ cols,
            const float* __restrict__ vals,
            const float* __restrict__ x,
            float* __restrict__ y) {
    unsigned idx = blockIdx.x * blockDim.x + threadIdx.x;
    unsigned e = idx >> 4;
    if (e >= E_NUM) return;
    unsigned part = (idx & 15u) * 4u;

    int   r = __ldg(rows + e);
    int   c = __ldg(cols + e);
    float v = __ldg(vals + e);

    float4 xv = *reinterpret_cast<const float4*>(x + (size_t)c * D + part);
    float* yp = y + (size_t)r * D + part;

    float a0 = v * xv.x, a1 = v * xv.y, a2 = v * xv.z, a3 = v * xv.w;
    asm volatile("red.global.add.v4.f32 [%0], {%1, %2, %3, %4};"
                 :: "l"(yp), "f"(a0), "f"(a1), "f"(a2), "f"(a3)
                 : "memory");
}

// ---------------------------------------------------------------------------
// out += src; tozero = 0  (prepares the other ping-pong buffer for next layer)
// ---------------------------------------------------------------------------
__global__ void addz_kernel(const float4* __restrict__ src,
                            float4* __restrict__ out,
                            float4* __restrict__ tozero) {
    const size_t total4 = (size_t)NN * D / 4;
    size_t idx = (size_t)blockIdx.x * blockDim.x + threadIdx.x;
    if (idx >= total4) return;
    float4 s = src[idx];
    float4 o = out[idx];
    o.x += s.x; o.y += s.y; o.z += s.z; o.w += s.w;
    out[idx] = o;
    tozero[idx] = make_float4(0.f, 0.f, 0.f, 0.f);
}

__global__ void add_kernel(const float4* __restrict__ src,
                           float4* __restrict__ out) {
    const size_t total4 = (size_t)NN * D / 4;
    size_t idx = (size_t)blockIdx.x * blockDim.x + threadIdx.x;
    if (idx >= total4) return;
    float4 s = src[idx];
    float4 o = out[idx];
    o.x += s.x; o.y += s.y; o.z += s.z; o.w += s.w;
    out[idx] = o;
}

extern "C" void kernel_launch(void* const* d_in, const int* in_sizes, int n_in,
                              void* d_out, int out_size) {
    const int*   rows = (const int*)  d_in[0];
    const int*   cols = (const int*)  d_in[1];
    const float* vals = (const float*)d_in[2];
    const float* uEmb = (const float*)d_in[3];
    const float* iEmb = (const float*)d_in[4];
    float* out = (float*)d_out;

    float* bufA; cudaGetSymbolAddress((void**)&bufA, g_bufA);
    float* bufB; cudaGetSymbolAddress((void**)&bufB, g_bufB);

    const size_t total4 = (size_t)NN * D / 4;          // 4.8M float4
    const int THREADS = 256;
    const int gridDense = (int)((total4 + THREADS - 1) / THREADS);
    const int gridSpmm  = (int)(((size_t)E_NUM * 16 + THREADS - 1) / THREADS);

    // out = acc0 = X0; bufA = X0; bufB = 0
    init_kernel<<<gridDense, THREADS>>>((const float4*)uEmb, (const float4*)iEmb,
                                        (float4*)out, (float4*)bufA, (float4*)bufB);
    // layer 1: B = A*Adj ; out += B ; A = 0
    spmm_kernel<<<gridSpmm, THREADS>>>(rows, cols, vals, bufA, bufB);
    addz_kernel<<<gridDense, THREADS>>>((const float4*)bufB, (float4*)out, (float4*)bufA);
    // layer 2: A = B*Adj ; out += A ; B = 0
    spmm_kernel<<<gridSpmm, THREADS>>>(rows, cols, vals, bufB, bufA);
    addz_kernel<<<gridDense, THREADS>>>((const float4*)bufA, (float4*)out, (float4*)bufB);
    // layer 3: B = A*Adj ; out += B
    spmm_kernel<<<gridSpmm, THREADS>>>(rows, cols, vals, bufA, bufB);
    add_kernel<<<gridDense, THREADS>>>((const float4*)bufB, (float4*)out);
}

// round 2
// speedup vs baseline: 1.0010x; 1.0010x over previous
#include <cuda_runtime.h>
#include <cstdint>

#define USER_N 100000
#define ITEM_N 200000
#define NN     (USER_N + ITEM_N)   // 300000
#define D      64
#define E_NUM  4800000

// Scratch ping-pong buffers for layer embeddings (static device allocation —
// the only legal scratch under the harness allocation guards).
__device__ float g_bufA[(size_t)NN * D];
__device__ float g_bufB[(size_t)NN * D];

// ---------------------------------------------------------------------------
// init: out = concat(u, i) (acc layer-0 term), bufA = same, bufB = 0
// float4-vectorized; USER_N*D and NN*D are multiples of 4.
// ---------------------------------------------------------------------------
__global__ void init_kernel(const float4* __restrict__ u,
                            const float4* __restrict__ i,
                            float4* __restrict__ out,
                            float4* __restrict__ bufA,
                            float4* __restrict__ bufB) {
    const size_t total4 = (size_t)NN * D / 4;
    const size_t usplit = (size_t)USER_N * D / 4;
    size_t idx = (size_t)blockIdx.x * blockDim.x + threadIdx.x;
    if (idx >= total4) return;
    float4 v = (idx < usplit) ? u[idx] : i[idx - usplit];
    out[idx]  = v;
    bufA[idx] = v;
    bufB[idx] = make_float4(0.f, 0.f, 0.f, 0.f);
}

// ---------------------------------------------------------------------------
// COO SpMM scatter: y[rows[e]] += vals[e] * x[cols[e]], 16 threads per edge,
// each thread owns a 16B (float4) slice and issues ONE red.global.add.v4.f32.
// ---------------------------------------------------------------------------
__global__ void __launch_bounds__(256)
spmm_kernel(const int* __restrict__ rows,
            const int* __restrict__ cols,
            const float* __restrict__ vals,
            const float* __restrict__ x,
            float* __restrict__ y) {
    unsigned idx = blockIdx.x * blockDim.x + threadIdx.x;
    unsigned e = idx >> 4;
    if (e >= E_NUM) return;
    unsigned part = (idx & 15u) * 4u;

    int   r = __ldg(rows + e);
    int   c = __ldg(cols + e);
    float v = __ldg(vals + e);

    float4 xv = *reinterpret_cast<const float4*>(x + (size_t)c * D + part);
    float* yp = y + (size_t)r * D + part;

    float a0 = v * xv.x, a1 = v * xv.y, a2 = v * xv.z, a3 = v * xv.w;
    asm volatile("red.global.add.v4.f32 [%0], {%1, %2, %3, %4};"
                 :: "l"(yp), "f"(a0), "f"(a1), "f"(a2), "f"(a3)
                 : "memory");
}

// ---------------------------------------------------------------------------
// out += src; tozero = 0  (prepares the other ping-pong buffer for next layer)
// ---------------------------------------------------------------------------
__global__ void addz_kernel(const float4* __restrict__ src,
                            float4* __restrict__ out,
                            float4* __restrict__ tozero) {
    const size_t total4 = (size_t)NN * D / 4;
    size_t idx = (size_t)blockIdx.x * blockDim.x + threadIdx.x;
    if (idx >= total4) return;
    float4 s = src[idx];
    float4 o = out[idx];
    o.x += s.x; o.y += s.y; o.z += s.z; o.w += s.w;
    out[idx] = o;
    tozero[idx] = make_float4(0.f, 0.f, 0.f, 0.f);
}

__global__ void add_kernel(const float4* __restrict__ src,
                           float4* __restrict__ out) {
    const size_t total4 = (size_t)NN * D / 4;
    size_t idx = (size_t)blockIdx.x * blockDim.x + threadIdx.x;
    if (idx >= total4) return;
    float4 s = src[idx];
    float4 o = out[idx];
    o.x += s.x; o.y += s.y; o.z += s.z; o.w += s.w;
    out[idx] = o;
}

extern "C" void kernel_launch(void* const* d_in, const int* in_sizes, int n_in,
                              void* d_out, int out_size) {
    const int*   rows = (const int*)  d_in[0];
    const int*   cols = (const int*)  d_in[1];
    const float* vals = (const float*)d_in[2];
    const float* uEmb = (const float*)d_in[3];
    const float* iEmb = (const float*)d_in[4];
    float* out = (float*)d_out;

    float* bufA; cudaGetSymbolAddress((void**)&bufA, g_bufA);
    float* bufB; cudaGetSymbolAddress((void**)&bufB, g_bufB);

    const size_t total4 = (size_t)NN * D / 4;          // 4.8M float4
    const int THREADS = 256;
    const int gridDense = (int)((total4 + THREADS - 1) / THREADS);
    const int gridSpmm  = (int)(((size_t)E_NUM * 16 + THREADS - 1) / THREADS);

    // out = acc0 = X0; bufA = X0; bufB = 0
    init_kernel<<<gridDense, THREADS>>>((const float4*)uEmb, (const float4*)iEmb,
                                        (float4*)out, (float4*)bufA, (float4*)bufB);
    // layer 1: B = A*Adj ; out += B ; A = 0
    spmm_kernel<<<gridSpmm, THREADS>>>(rows, cols, vals, bufA, bufB);
    addz_kernel<<<gridDense, THREADS>>>((const float4*)bufB, (float4*)out, (float4*)bufA);
    // layer 2: A = B*Adj ; out += A ; B = 0
    spmm_kernel<<<gridSpmm, THREADS>>>(rows, cols, vals, bufB, bufA);
    addz_kernel<<<gridDense, THREADS>>>((const float4*)bufA, (float4*)out, (float4*)bufB);
    // layer 3: B = A*Adj ; out += B
    spmm_kernel<<<gridSpmm, THREADS>>>(rows, cols, vals, bufA, bufB);
    add_kernel<<<gridDense, THREADS>>>((const float4*)bufB, (float4*)out);
}

// round 3
// speedup vs baseline: 1.1748x; 1.1736x over previous
#include <cuda_runtime.h>
#include <cstdint>

#define USER_N 100000
#define ITEM_N 200000
#define NN     (USER_N + ITEM_N)   // 300000
#define D      64
#define E_NUM  4800000

// Scratch ping-pong buffers (static device allocation — only legal scratch).
__device__ float g_bufA[(size_t)NN * D];
__device__ float g_bufB[(size_t)NN * D];

// ---------------------------------------------------------------------------
// init: out = concat(u, i) (layer-0 acc term), bufA = same, bufB = 0
// ---------------------------------------------------------------------------
__global__ void init_kernel(const float4* __restrict__ u,
                            const float4* __restrict__ i,
                            float4* __restrict__ out,
                            float4* __restrict__ bufA,
                            float4* __restrict__ bufB) {
    const unsigned total4 = NN * D / 4;
    const unsigned usplit = USER_N * D / 4;
    unsigned idx = blockIdx.x * blockDim.x + threadIdx.x;
    if (idx >= total4) return;
    float4 v = (idx < usplit) ? u[idx] : i[idx - usplit];
    out[idx]  = v;
    bufA[idx] = v;
    bufB[idx] = make_float4(0.f, 0.f, 0.f, 0.f);
}

// ---------------------------------------------------------------------------
// Half-D COO SpMM scatter: handles a 32-float (one 128B line) slice of every
// row. x and y are pre-offset by half*32 on the host side. 8 threads/edge,
// one float4 gather + one red.global.add.v4.f32 each.
// Randomly-touched footprint per pass = 2 x 38.4MB -> L2-resident.
// ---------------------------------------------------------------------------
__global__ void __launch_bounds__(256)
spmm_half_kernel(const int* __restrict__ rows,
                 const int* __restrict__ cols,
                 const float* __restrict__ vals,
                 const float* __restrict__ x,   // + half*32
                 float* __restrict__ y) {       // + half*32
    unsigned idx = blockIdx.x * blockDim.x + threadIdx.x;
    unsigned e = idx >> 3;
    if (e >= E_NUM) return;
    unsigned part = (idx & 7u) << 2;           // 0,4,...,28

    unsigned r = (unsigned)__ldg(rows + e);
    unsigned c = (unsigned)__ldg(cols + e);
    float    v = __ldg(vals + e);

    float4 xv = *reinterpret_cast<const float4*>(x + c * (unsigned)D + part);
    float* yp = y + r * (unsigned)D + part;

    float a0 = v * xv.x, a1 = v * xv.y, a2 = v * xv.z, a3 = v * xv.w;
    asm volatile("red.global.add.v4.f32 [%0], {%1, %2, %3, %4};"
                 :: "l"(yp), "f"(a0), "f"(a1), "f"(a2), "f"(a3)
                 : "memory");
}

// ---------------------------------------------------------------------------
// out += src ; tozero = 0   (fused accumulate + next-layer zero)
// ---------------------------------------------------------------------------
__global__ void addz_kernel(const float4* __restrict__ src,
                            float4* __restrict__ out,
                            float4* __restrict__ tozero) {
    const unsigned total4 = NN * D / 4;
    unsigned idx = blockIdx.x * blockDim.x + threadIdx.x;
    if (idx >= total4) return;
    float4 s = src[idx];
    float4 o = out[idx];
    o.x += s.x; o.y += s.y; o.z += s.z; o.w += s.w;
    out[idx] = o;
    tozero[idx] = make_float4(0.f, 0.f, 0.f, 0.f);
}

// out += src (no zeroing — layer 3 scatters straight into out)
__global__ void add_kernel(const float4* __restrict__ src,
                           float4* __restrict__ out) {
    const unsigned total4 = NN * D / 4;
    unsigned idx = blockIdx.x * blockDim.x + threadIdx.x;
    if (idx >= total4) return;
    float4 s = src[idx];
    float4 o = out[idx];
    o.x += s.x; o.y += s.y; o.z += s.z; o.w += s.w;
    out[idx] = o;
}

extern "C" void kernel_launch(void* const* d_in, const int* in_sizes, int n_in,
                              void* d_out, int out_size) {
    const int*   rows = (const int*)  d_in[0];
    const int*   cols = (const int*)  d_in[1];
    const float* vals = (const float*)d_in[2];
    const float* uEmb = (const float*)d_in[3];
    const float* iEmb = (const float*)d_in[4];
    float* out = (float*)d_out;

    float* bufA; cudaGetSymbolAddress((void**)&bufA, g_bufA);
    float* bufB; cudaGetSymbolAddress((void**)&bufB, g_bufB);

    const int THREADS = 256;
    const unsigned total4 = NN * D / 4;
    const int gridDense = (int)((total4 + THREADS - 1) / THREADS);
    const int gridSpmm  = (int)(((size_t)E_NUM * 8 + THREADS - 1) / THREADS);

    // out = acc0 = X0 ; bufA = X0 ; bufB = 0
    init_kernel<<<gridDense, THREADS>>>((const float4*)uEmb, (const float4*)iEmb,
                                        (float4*)out, (float4*)bufA, (float4*)bufB);

    // layer 1: B = Adj*A (two L2-resident half passes); out += B ; A = 0
    spmm_half_kernel<<<gridSpmm, THREADS>>>(rows, cols, vals, bufA,      bufB);
    spmm_half_kernel<<<gridSpmm, THREADS>>>(rows, cols, vals, bufA + 32, bufB + 32);
    addz_kernel<<<gridDense, THREADS>>>((const float4*)bufB, (float4*)out, (float4*)bufA);

    // layer 2: A = Adj*B ; out += A
    spmm_half_kernel<<<gridSpmm, THREADS>>>(rows, cols, vals, bufB,      bufA);
    spmm_half_kernel<<<gridSpmm, THREADS>>>(rows, cols, vals, bufB + 32, bufA + 32);
    add_kernel<<<gridDense, THREADS>>>((const float4*)bufA, (float4*)out);

    // layer 3: out += Adj*A   (scatter directly into the accumulator)
    spmm_half_kernel<<<gridSpmm, THREADS>>>(rows, cols, vals, bufA,      out);
    spmm_half_kernel<<<gridSpmm, THREADS>>>(rows, cols, vals, bufA + 32, out + 32);
}